// round 1
// baseline (speedup 1.0000x reference)
#include <cuda_runtime.h>

#define N_CELL 50000
#define N_NET  10000
#define N_GCELL 20000
#define NE 100000
#define D 32
#define DP 16

// output layout: h_cell [N_CELL*D] | h_net [N_NET*D] | h_gcell [N_GCELL*D]
#define OUT_NET_OFF   (N_CELL*D)            // 1,600,000
#define OUT_GCELL_OFF ((N_CELL+N_NET)*D)    // 1,920,000

// degree counter layout inside g_cnt
#define CNT_PINS_SRC   0         // N_CELL
#define CNT_PINS_DST   50000     // N_NET
#define CNT_PINNED_DST 60000     // N_CELL
#define CNT_CONN_SRC   110000    // N_GCELL
#define CNT_CONN_DST   130000    // N_GCELL
#define CNT_PT_SRC     150000    // N_CELL
#define CNT_PT_DST     200000    // N_GCELL
#define CNT_PF_DST     220000    // N_CELL
#define CNT_TOTAL      270000

// ---------------- scratch (device globals; no allocation allowed) ----------
__device__ int   g_cnt[CNT_TOTAL];
__device__ float g_feat_pins[N_CELL*D];
__device__ float g_feat_pt[N_CELL*D];
__device__ float g_feat_conn[N_GCELL*D];
__device__ float g_Mnet[N_NET*DP*D];     // [n][p][o]
__device__ float g_cnet[N_NET*D];
__device__ float g_Mhan[N_GCELL*DP*D];
__device__ float g_chan[N_GCELL*D];

__device__ __forceinline__ void red_add_v4(float* p, float4 v) {
    asm volatile("red.global.add.v4.f32 [%0], {%1,%2,%3,%4};"
                 :: "l"(p), "f"(v.x), "f"(v.y), "f"(v.z), "f"(v.w) : "memory");
}

// ---------------- init ----------------
__global__ void zero_cnt_kernel() {
    int i = blockIdx.x * blockDim.x + threadIdx.x;
    if (i < CNT_TOTAL) g_cnt[i] = 0;
}

// ---------------- degree counting ----------------
__global__ void count_kernel(const int* __restrict__ pins_src, const int* __restrict__ pins_dst,
                             const int* __restrict__ pinned_dst,
                             const int* __restrict__ conn_src, const int* __restrict__ conn_dst,
                             const int* __restrict__ pt_src, const int* __restrict__ pt_dst,
                             const int* __restrict__ pf_dst) {
    int e = blockIdx.x * blockDim.x + threadIdx.x;
    if (e >= NE) return;
    atomicAdd(&g_cnt[CNT_PINS_SRC   + pins_src[e]],   1);
    atomicAdd(&g_cnt[CNT_PINS_DST   + pins_dst[e]],   1);
    atomicAdd(&g_cnt[CNT_PINNED_DST + pinned_dst[e]], 1);
    atomicAdd(&g_cnt[CNT_CONN_SRC   + conn_src[e]],   1);
    atomicAdd(&g_cnt[CNT_CONN_DST   + conn_dst[e]],   1);
    atomicAdd(&g_cnt[CNT_PT_SRC     + pt_src[e]],     1);
    atomicAdd(&g_cnt[CNT_PT_DST     + pt_dst[e]],     1);
    atomicAdd(&g_cnt[CNT_PF_DST     + pf_dst[e]],     1);
}

// ------------- node features: feat_pins = (node*s1)@W_pins, feat_pt = (node*s2)@W_pt -------------
__global__ void node_feat_kernel(const float* __restrict__ node_feat,
                                 const float* __restrict__ Wp, const float* __restrict__ Wt) {
    __shared__ float sWp[D*D], sWt[D*D];
    for (int i = threadIdx.x; i < D*D; i += blockDim.x) { sWp[i] = Wp[i]; sWt[i] = Wt[i]; }
    __syncthreads();
    int wid = threadIdx.x >> 5, lane = threadIdx.x & 31;
    int row = blockIdx.x * 8 + wid;
    if (row >= N_CELL) return;
    float h = node_feat[row*D + lane];
    float a1 = 0.f, a2 = 0.f;
#pragma unroll
    for (int i = 0; i < D; i++) {
        float hi = __shfl_sync(0xffffffffu, h, i);
        a1 += hi * sWp[i*D + lane];
        a2 += hi * sWt[i*D + lane];
    }
    float s1 = rsqrtf((float)max(g_cnt[CNT_PINS_SRC + row], 1));
    float s2 = rsqrtf((float)max(g_cnt[CNT_PT_SRC + row], 1));
    g_feat_pins[row*D + lane] = a1 * s1;
    g_feat_pt[row*D + lane]   = a2 * s2;
}

// ------------- gcell features: feat_conn = (hanna*s)@W_connect -------------
__global__ void conn_feat_kernel(const float* __restrict__ hanna_feat,
                                 const float* __restrict__ Wc) {
    __shared__ float sW[D*D];
    for (int i = threadIdx.x; i < D*D; i += blockDim.x) sW[i] = Wc[i];
    __syncthreads();
    int wid = threadIdx.x >> 5, lane = threadIdx.x & 31;
    int row = blockIdx.x * 8 + wid;
    if (row >= N_GCELL) return;
    float h = hanna_feat[row*D + lane];
    float a = 0.f;
#pragma unroll
    for (int i = 0; i < D; i++) {
        float hi = __shfl_sync(0xffffffffu, h, i);
        a += hi * sW[i*D + lane];
    }
    float s = rsqrtf((float)max(g_cnt[CNT_CONN_SRC + row], 1));
    g_feat_conn[row*D + lane] = a * s;
}

// ------------- per-node NNConv matrices: M_n[p,o] = sum_i h_n[i]*W_topo[p, i*D+o] -------------
// 4 rows per warp (register tiling to amortize shared loads of W_topo)
__global__ void m_kernel(const float* __restrict__ net_feat, const float* __restrict__ hanna_feat,
                         const float* __restrict__ W_topo, const float* __restrict__ b_topo) {
    extern __shared__ float s[];
    float* sW = s;               // DP * D*D = 16384 floats
    float* sb = s + DP*D*D;      // D*D = 1024 floats
    for (int i = threadIdx.x; i < DP*D*D; i += blockDim.x) sW[i] = W_topo[i];
    for (int i = threadIdx.x; i < D*D; i += blockDim.x)    sb[i] = b_topo[i];
    __syncthreads();
    int wid = threadIdx.x >> 5, lane = threadIdx.x & 31;
    int g = blockIdx.x * 8 + wid;     // group of 4 rows
    int r0 = g * 4;
    const int NTOT = N_NET + N_GCELL;
    if (r0 >= NTOT) return;

    float h[4];
    float* Mout[4];
    float* cout[4];
#pragma unroll
    for (int r = 0; r < 4; r++) {
        int row = r0 + r;
        if (row < N_NET) {
            h[r] = net_feat[row*D + lane];
            Mout[r] = g_Mnet + (size_t)row * (DP*D);
            cout[r] = g_cnet + (size_t)row * D;
        } else {
            int rr = row - N_NET;
            h[r] = hanna_feat[rr*D + lane];
            Mout[r] = g_Mhan + (size_t)rr * (DP*D);
            cout[r] = g_chan + (size_t)rr * D;
        }
    }

    float acc[4][DP];
    float accc[4];
#pragma unroll
    for (int r = 0; r < 4; r++) {
        accc[r] = 0.f;
#pragma unroll
        for (int p = 0; p < DP; p++) acc[r][p] = 0.f;
    }

#pragma unroll
    for (int i = 0; i < D; i++) {
        float hi[4];
#pragma unroll
        for (int r = 0; r < 4; r++) hi[r] = __shfl_sync(0xffffffffu, h[r], i);
        float bv = sb[i*D + lane];
#pragma unroll
        for (int r = 0; r < 4; r++) accc[r] += hi[r] * bv;
#pragma unroll
        for (int p = 0; p < DP; p++) {
            float wv = sW[p*(D*D) + i*D + lane];
#pragma unroll
            for (int r = 0; r < 4; r++) acc[r][p] += hi[r] * wv;
        }
    }

#pragma unroll
    for (int r = 0; r < 4; r++) {
#pragma unroll
        for (int p = 0; p < DP; p++) Mout[r][p*D + lane] = acc[r][p];
        cout[r][lane] = accc[r];
    }
}

// ------------- GraphConv edge scatter: out[dst] += feat[src] * deg_dst^-1/2 -------------
// which: 0 = pins (-> net), 1 = connect (-> gcell), 2 = pt (-> gcell)
__global__ void gc_edge_kernel(int which, const int* __restrict__ src, const int* __restrict__ dst,
                               float* __restrict__ out) {
    int t = blockIdx.x * blockDim.x + threadIdx.x;
    int e = t >> 3, j = t & 7;
    if (e >= NE) return;
    const float* feat;
    const int* cnt;
    if (which == 0)      { feat = g_feat_pins; cnt = g_cnt + CNT_PINS_DST; }
    else if (which == 1) { feat = g_feat_conn; cnt = g_cnt + CNT_CONN_DST; }
    else                 { feat = g_feat_pt;   cnt = g_cnt + CNT_PT_DST; }
    int s = src[e], d = dst[e];
    float w = rsqrtf((float)max(cnt[d], 1));
    float4 v = *reinterpret_cast<const float4*>(feat + (size_t)s*D + j*4);
    v.x *= w; v.y *= w; v.z *= w; v.w *= w;
    red_add_v4(out + (size_t)d*D + j*4, v);
}

// ------------- NNConv edge scatter: out[dst] += (ef @ M_src + c_src) / deg_dst -------------
// which: 0 = pinned (net->cell, pin_feat), 1 = pf (gcell->cell, edge_feat)
__global__ void nn_edge_kernel(int which, const float* __restrict__ ef,
                               const int* __restrict__ src, const int* __restrict__ dst,
                               float* __restrict__ out_cell) {
    int t = blockIdx.x * blockDim.x + threadIdx.x;
    int e = t >> 3, j = t & 7;
    if (e >= NE) return;
    const float* M; const float* c; const int* cnt;
    if (which == 0) { M = g_Mnet; c = g_cnet; cnt = g_cnt + CNT_PINNED_DST; }
    else            { M = g_Mhan; c = g_chan; cnt = g_cnt + CNT_PF_DST; }
    int s = src[e], d = dst[e];
    float inv = 1.f / (float)max(cnt[d], 1);

    const float4* efp = reinterpret_cast<const float4*>(ef + (size_t)e * DP);
    float4 e0 = efp[0], e1 = efp[1], e2 = efp[2], e3 = efp[3];
    float efv[DP] = { e0.x, e0.y, e0.z, e0.w, e1.x, e1.y, e1.z, e1.w,
                      e2.x, e2.y, e2.z, e2.w, e3.x, e3.y, e3.z, e3.w };

    const float* Mrow = M + (size_t)s * (DP*D) + j*4;
    float4 acc = *reinterpret_cast<const float4*>(c + (size_t)s*D + j*4);
#pragma unroll
    for (int p = 0; p < DP; p++) {
        float4 mv = *reinterpret_cast<const float4*>(Mrow + p*D);
        acc.x += efv[p] * mv.x; acc.y += efv[p] * mv.y;
        acc.z += efv[p] * mv.z; acc.w += efv[p] * mv.w;
    }
    acc.x *= inv; acc.y *= inv; acc.z *= inv; acc.w *= inv;
    red_add_v4(out_cell + (size_t)d*D + j*4, acc);
}

// ------------- finalize: biases for cell & gcell regions -------------
__global__ void bias_kernel(const float* __restrict__ b_pinned, const float* __restrict__ b_pf,
                            const float* __restrict__ b_connect, const float* __restrict__ b_pt,
                            float* __restrict__ out) {
    int i = blockIdx.x * blockDim.x + threadIdx.x;
    const int n_cell_el = N_CELL * D;
    const int n_gcell_el = N_GCELL * D;
    if (i < n_cell_el) {
        int o = i & (D-1);
        out[i] += b_pinned[o] + b_pf[o];
    } else if (i < n_cell_el + n_gcell_el) {
        int k = i - n_cell_el;
        int o = k & (D-1);
        out[OUT_GCELL_OFF + k] += b_connect[o] + b_pt[o];
    }
}

// ------------- finalize net: out_net += net_feat @ W_net + b_net + b_pins -------------
__global__ void net_final_kernel(const float* __restrict__ net_feat, const float* __restrict__ W_net,
                                 const float* __restrict__ b_net, const float* __restrict__ b_pins,
                                 float* __restrict__ out_net) {
    __shared__ float sW[D*D];
    for (int i = threadIdx.x; i < D*D; i += blockDim.x) sW[i] = W_net[i];
    __syncthreads();
    int wid = threadIdx.x >> 5, lane = threadIdx.x & 31;
    int row = blockIdx.x * 8 + wid;
    if (row >= N_NET) return;
    float h = net_feat[row*D + lane];
    float a = b_net[lane] + b_pins[lane];
#pragma unroll
    for (int i = 0; i < D; i++) {
        float hi = __shfl_sync(0xffffffffu, h, i);
        a += hi * sW[i*D + lane];
    }
    out_net[row*D + lane] += a;
}

extern "C" void kernel_launch(void* const* d_in, const int* in_sizes, int n_in,
                              void* d_out, int out_size) {
    const float* node_feat  = (const float*)d_in[0];
    const float* net_feat   = (const float*)d_in[1];
    const float* pin_feat   = (const float*)d_in[2];
    const float* hanna_feat = (const float*)d_in[3];
    const float* edge_feat  = (const float*)d_in[4];
    const int* pins_src     = (const int*)d_in[5];
    const int* pins_dst     = (const int*)d_in[6];
    const int* pinned_src   = (const int*)d_in[7];
    const int* pinned_dst   = (const int*)d_in[8];
    const int* connect_src  = (const int*)d_in[9];
    const int* connect_dst  = (const int*)d_in[10];
    const int* pt_src       = (const int*)d_in[11];
    const int* pt_dst       = (const int*)d_in[12];
    const int* pf_src       = (const int*)d_in[13];
    const int* pf_dst       = (const int*)d_in[14];
    const float* W_net      = (const float*)d_in[15];
    const float* b_net      = (const float*)d_in[16];
    const float* W_topo     = (const float*)d_in[17];
    const float* b_topo     = (const float*)d_in[18];
    const float* W_pins     = (const float*)d_in[19];
    const float* b_pins     = (const float*)d_in[20];
    const float* W_connect  = (const float*)d_in[21];
    const float* b_connect  = (const float*)d_in[22];
    const float* W_pt       = (const float*)d_in[23];
    const float* b_pt       = (const float*)d_in[24];
    const float* b_pinned   = (const float*)d_in[25];
    const float* b_pf       = (const float*)d_in[26];
    (void)pinned_src; (void)pf_src; (void)in_sizes; (void)n_in;

    float* out = (float*)d_out;
    float* out_cell  = out;
    float* out_net   = out + OUT_NET_OFF;
    float* out_gcell = out + OUT_GCELL_OFF;

    // zero accumulators (output) and degree counters
    cudaMemsetAsync(d_out, 0, (size_t)out_size * sizeof(float));
    zero_cnt_kernel<<<(CNT_TOTAL + 255)/256, 256>>>();

    // degrees
    count_kernel<<<(NE + 255)/256, 256>>>(pins_src, pins_dst, pinned_dst,
                                          connect_src, connect_dst, pt_src, pt_dst, pf_dst);

    // per-node GEMM precomputes
    node_feat_kernel<<<(N_CELL + 7)/8, 256>>>(node_feat, W_pins, W_pt);
    conn_feat_kernel<<<(N_GCELL + 7)/8, 256>>>(hanna_feat, W_connect);

    static bool attr_set = false;
    size_t m_smem = (size_t)(DP*D*D + D*D) * sizeof(float); // 69632 bytes
    if (!attr_set) {
        cudaFuncSetAttribute(m_kernel, cudaFuncAttributeMaxDynamicSharedMemorySize, (int)m_smem);
        attr_set = true;
    }
    int n_groups = (N_NET + N_GCELL + 3) / 4;   // 7500
    m_kernel<<<(n_groups + 7)/8, 256, m_smem>>>(net_feat, hanna_feat, W_topo, b_topo);

    // edge scatters (pre-scaled; accumulate into d_out)
    const int edge_blocks = (NE * 8 + 255) / 256;
    gc_edge_kernel<<<edge_blocks, 256>>>(0, pins_src, pins_dst, out_net);
    gc_edge_kernel<<<edge_blocks, 256>>>(1, connect_src, connect_dst, out_gcell);
    gc_edge_kernel<<<edge_blocks, 256>>>(2, pt_src, pt_dst, out_gcell);
    nn_edge_kernel<<<edge_blocks, 256>>>(0, pin_feat, pinned_src, pinned_dst, out_cell);
    nn_edge_kernel<<<edge_blocks, 256>>>(1, edge_feat, pf_src, pf_dst, out_cell);

    // finalize
    bias_kernel<<<((N_CELL + N_GCELL)*D + 255)/256, 256>>>(b_pinned, b_pf, b_connect, b_pt, out);
    net_final_kernel<<<(N_NET + 7)/8, 256>>>(net_feat, W_net, b_net, b_pins, out_net);
}

// round 3
// speedup vs baseline: 1.2009x; 1.2009x over previous
#include <cuda_runtime.h>

#define N_CELL 50000
#define N_NET  10000
#define N_GCELL 20000
#define NE 100000
#define D 32
#define DP 16

#define OUT_NET_OFF   (N_CELL*D)            // 1,600,000
#define OUT_GCELL_OFF ((N_CELL+N_NET)*D)    // 1,920,000

// degree counter layout inside g_cnt
#define CNT_PINS_SRC   0         // N_CELL
#define CNT_PINS_DST   50000     // N_NET
#define CNT_PINNED_DST 60000     // N_CELL
#define CNT_CONN_SRC   110000    // N_GCELL
#define CNT_CONN_DST   130000    // N_GCELL
#define CNT_PT_SRC     150000    // N_CELL
#define CNT_PT_DST     200000    // N_GCELL
#define CNT_PF_DST     220000    // N_CELL
#define CNT_TOTAL      270000

#define WT_PAD 18                 // [i][o][p] smem layout, o-stride 18 (16 p + 2 pad)
#define WT_SIZE (D * D * WT_PAD)  // 18432 floats

// ---------------- scratch (device globals; no allocation allowed) ----------
__device__ int   g_cnt[CNT_TOTAL];
__device__ float g_feat_pins[N_CELL*D];   // node @ W_pins (unscaled)
__device__ float g_feat_pt[N_CELL*D];     // node @ W_pt   (unscaled)
__device__ float g_feat_conn[N_GCELL*D];  // hanna @ W_connect (unscaled)
__device__ float g_Mnet[N_NET*DP*D];      // [n][p][o]
__device__ float g_cnet[N_NET*D];
__device__ float g_Mhan[N_GCELL*DP*D];
__device__ float g_chan[N_GCELL*D];

__device__ __forceinline__ void red_add_v4(float* p, float4 v) {
    asm volatile("red.global.add.v4.f32 [%0], {%1,%2,%3,%4};"
                 :: "l"(p), "f"(v.x), "f"(v.y), "f"(v.z), "f"(v.w) : "memory");
}
__device__ __forceinline__ unsigned long long pack2(float x, float y) {
    unsigned long long r;
    asm("mov.b64 %0, {%1,%2};" : "=l"(r) : "f"(x), "f"(y));
    return r;
}
__device__ __forceinline__ void unpack2(unsigned long long v, float& x, float& y) {
    asm("mov.b64 {%0,%1}, %2;" : "=f"(x), "=f"(y) : "l"(v));
}
__device__ __forceinline__ unsigned long long fma2(unsigned long long a,
                                                   unsigned long long b,
                                                   unsigned long long c) {
    unsigned long long d;
    asm("fma.rn.f32x2 %0, %1, %2, %3;" : "=l"(d) : "l"(a), "l"(b), "l"(c));
    return d;
}

// =============== fused prep: count | bias init | net init | node feats | conn feats ========
#define B_COUNT 391                                     // ceil(NE/256)
#define B_BIAS  8750                                    // (N_CELL+N_GCELL)*D / 256
#define B_NET   1250                                    // N_NET / 8
#define B_NODE  6250                                    // N_CELL / 8
#define B_CONN  2500                                    // N_GCELL / 8
#define B_PREP  (B_COUNT + B_BIAS + B_NET + B_NODE + B_CONN)   // 19141

__global__ void prep_kernel(const int* __restrict__ pins_src, const int* __restrict__ pins_dst,
                            const int* __restrict__ pinned_dst,
                            const int* __restrict__ conn_src, const int* __restrict__ conn_dst,
                            const int* __restrict__ pt_src, const int* __restrict__ pt_dst,
                            const int* __restrict__ pf_dst,
                            const float* __restrict__ node_feat, const float* __restrict__ net_feat,
                            const float* __restrict__ hanna_feat,
                            const float* __restrict__ W_net, const float* __restrict__ b_net,
                            const float* __restrict__ W_pins, const float* __restrict__ b_pins,
                            const float* __restrict__ W_connect, const float* __restrict__ b_connect,
                            const float* __restrict__ W_pt, const float* __restrict__ b_pt,
                            const float* __restrict__ b_pinned, const float* __restrict__ b_pf,
                            float* __restrict__ out) {
    __shared__ float sA[D*D], sB[D*D];
    int b = blockIdx.x;

    if (b < B_COUNT) {
        // ---- degree counting ----
        int e = b * 256 + threadIdx.x;
        if (e >= NE) return;
        atomicAdd(&g_cnt[CNT_PINS_SRC   + pins_src[e]],   1);
        atomicAdd(&g_cnt[CNT_PINS_DST   + pins_dst[e]],   1);
        atomicAdd(&g_cnt[CNT_PINNED_DST + pinned_dst[e]], 1);
        atomicAdd(&g_cnt[CNT_CONN_SRC   + conn_src[e]],   1);
        atomicAdd(&g_cnt[CNT_CONN_DST   + conn_dst[e]],   1);
        atomicAdd(&g_cnt[CNT_PT_SRC     + pt_src[e]],     1);
        atomicAdd(&g_cnt[CNT_PT_DST     + pt_dst[e]],     1);
        atomicAdd(&g_cnt[CNT_PF_DST     + pf_dst[e]],     1);
        return;
    }
    b -= B_COUNT;

    if (b < B_BIAS) {
        // ---- bias init of cell + gcell output regions ----
        int i = b * 256 + threadIdx.x;
        const int n_cell_el = N_CELL * D;
        int o = i & (D-1);
        if (i < n_cell_el) {
            out[i] = b_pinned[o] + b_pf[o];
        } else {
            int k = i - n_cell_el;
            out[OUT_GCELL_OFF + k] = b_connect[o] + b_pt[o];
        }
        return;
    }
    b -= B_BIAS;

    int wid = threadIdx.x >> 5, lane = threadIdx.x & 31;

    if (b < B_NET) {
        // ---- out_net = net_feat @ W_net + b_net + b_pins ----
        for (int i = threadIdx.x; i < D*D; i += 256) sA[i] = W_net[i];
        __syncthreads();
        int row = b * 8 + wid;
        float h = net_feat[row*D + lane];
        float a = b_net[lane] + b_pins[lane];
#pragma unroll
        for (int i = 0; i < D; i++) {
            float hi = __shfl_sync(0xffffffffu, h, i);
            a += hi * sA[i*D + lane];
        }
        out[OUT_NET_OFF + row*D + lane] = a;
        return;
    }
    b -= B_NET;

    if (b < B_NODE) {
        // ---- node feats: g_feat_pins = node@W_pins, g_feat_pt = node@W_pt ----
        for (int i = threadIdx.x; i < D*D; i += 256) { sA[i] = W_pins[i]; sB[i] = W_pt[i]; }
        __syncthreads();
        int row = b * 8 + wid;
        float h = node_feat[row*D + lane];
        float a1 = 0.f, a2 = 0.f;
#pragma unroll
        for (int i = 0; i < D; i++) {
            float hi = __shfl_sync(0xffffffffu, h, i);
            a1 += hi * sA[i*D + lane];
            a2 += hi * sB[i*D + lane];
        }
        g_feat_pins[row*D + lane] = a1;
        g_feat_pt[row*D + lane]   = a2;
        return;
    }
    b -= B_NODE;

    // ---- gcell feats: g_feat_conn = hanna@W_connect ----
    for (int i = threadIdx.x; i < D*D; i += 256) sA[i] = W_connect[i];
    __syncthreads();
    int row = b * 8 + wid;
    float h = hanna_feat[row*D + lane];
    float a = 0.f;
#pragma unroll
    for (int i = 0; i < D; i++) {
        float hi = __shfl_sync(0xffffffffu, h, i);
        a += hi * sA[i*D + lane];
    }
    g_feat_conn[row*D + lane] = a;
}

// ------------- per-node NNConv matrices via packed f32x2 ------------------------
// M_n[p,o] = sum_i h_n[i]*W_topo[p, i*D+o];   c_n[o] = sum_i h_n[i]*b_topo[i*D+o]
// W_topo transposed to [i][o][p] directly during the smem load.
#define MR 4
__global__ void m2_kernel(const float* __restrict__ net_feat, const float* __restrict__ hanna_feat,
                          const float* __restrict__ W_topo, const float* __restrict__ b_topo) {
    extern __shared__ float s[];
    float* sW2 = s;                 // WT_SIZE = 18432 floats
    float* sb  = s + WT_SIZE;       // 1024
    float* sH  = s + WT_SIZE + D*D; // 8 warps * MR * 32 = 1024
    for (int t = threadIdx.x; t < DP*D*D; t += blockDim.x) {
        int p = t >> 10;          // t / (D*D)
        int rem = t & 1023;
        int i = rem >> 5;
        int o = rem & 31;
        sW2[i*(D*WT_PAD) + o*WT_PAD + p] = W_topo[t];
    }
    for (int i = threadIdx.x; i < D*D; i += blockDim.x) sb[i] = b_topo[i];
    __syncthreads();

    int wid = threadIdx.x >> 5, lane = threadIdx.x & 31;
    int g = blockIdx.x * 8 + wid;            // group of MR rows
    const int NGROUPS = (N_NET + N_GCELL) / MR;  // 7500
    if (g >= NGROUPS) return;
    int r0 = g * MR;
    int hbase = wid * (MR*32);

    float* Mout[MR];
    float* cout[MR];
#pragma unroll
    for (int r = 0; r < MR; r++) {
        int row = r0 + r;
        float hv;
        if (row < N_NET) {
            hv = net_feat[row*D + lane];
            Mout[r] = g_Mnet + (size_t)row * (DP*D);
            cout[r] = g_cnet + (size_t)row * D;
        } else {
            int rr = row - N_NET;
            hv = hanna_feat[rr*D + lane];
            Mout[r] = g_Mhan + (size_t)rr * (DP*D);
            cout[r] = g_chan + (size_t)rr * D;
        }
        sH[hbase + r*32 + lane] = hv;
    }
    __syncwarp();

    unsigned long long acc[MR][DP/2];
    float cacc[MR];
#pragma unroll
    for (int r = 0; r < MR; r++) {
        cacc[r] = 0.f;
#pragma unroll
        for (int pp = 0; pp < DP/2; pp++) acc[r][pp] = 0ull;
    }

#pragma unroll
    for (int i = 0; i < D; i++) {
        unsigned long long hp[MR];
        float bv = sb[i*D + lane];
#pragma unroll
        for (int r = 0; r < MR; r++) {
            float hv = sH[hbase + r*32 + i];
            hp[r] = pack2(hv, hv);
            cacc[r] += hv * bv;
        }
        const unsigned long long* wrow =
            reinterpret_cast<const unsigned long long*>(sW2 + i*(D*WT_PAD) + lane*WT_PAD);
#pragma unroll
        for (int pp = 0; pp < DP/2; pp++) {
            unsigned long long wv = wrow[pp];
#pragma unroll
            for (int r = 0; r < MR; r++) acc[r][pp] = fma2(hp[r], wv, acc[r][pp]);
        }
    }

#pragma unroll
    for (int r = 0; r < MR; r++) {
#pragma unroll
        for (int pp = 0; pp < DP/2; pp++) {
            float x, y;
            unpack2(acc[r][pp], x, y);
            Mout[r][(2*pp)*D + lane]   = x;
            Mout[r][(2*pp+1)*D + lane] = y;
        }
        cout[r][lane] = cacc[r];
    }
}

// ------------- fused edge scatter: blocks [0,B_EDGE) = GraphConvs, [B_EDGE,2*B_EDGE) = NNConvs ----
#define B_EDGE 3125                                     // NE*8/256

__global__ void edge_kernel(const int* __restrict__ pins_src, const int* __restrict__ pins_dst,
                            const int* __restrict__ conn_src, const int* __restrict__ conn_dst,
                            const int* __restrict__ pt_src, const int* __restrict__ pt_dst,
                            const float* __restrict__ pin_feat,
                            const int* __restrict__ pinned_src, const int* __restrict__ pinned_dst,
                            const float* __restrict__ edge_feat,
                            const int* __restrict__ pf_src, const int* __restrict__ pf_dst,
                            float* __restrict__ out) {
    int b = blockIdx.x;
    if (b < B_EDGE) {
        // ---- GraphConv scatters ----
        int t = b * 256 + threadIdx.x;
        int e = t >> 3, j = t & 7;
        float* out_net   = out + OUT_NET_OFF;
        float* out_gcell = out + OUT_GCELL_OFF;
        // pins: cell -> net
        {
            int sI = pins_src[e], dI = pins_dst[e];
            float w = rsqrtf((float)max(g_cnt[CNT_PINS_SRC + sI], 1)) *
                      rsqrtf((float)max(g_cnt[CNT_PINS_DST + dI], 1));
            float4 v = *reinterpret_cast<const float4*>(g_feat_pins + (size_t)sI*D + j*4);
            v.x *= w; v.y *= w; v.z *= w; v.w *= w;
            red_add_v4(out_net + (size_t)dI*D + j*4, v);
        }
        // connect: gcell -> gcell
        {
            int sI = conn_src[e], dI = conn_dst[e];
            float w = rsqrtf((float)max(g_cnt[CNT_CONN_SRC + sI], 1)) *
                      rsqrtf((float)max(g_cnt[CNT_CONN_DST + dI], 1));
            float4 v = *reinterpret_cast<const float4*>(g_feat_conn + (size_t)sI*D + j*4);
            v.x *= w; v.y *= w; v.z *= w; v.w *= w;
            red_add_v4(out_gcell + (size_t)dI*D + j*4, v);
        }
        // pt: cell -> gcell
        {
            int sI = pt_src[e], dI = pt_dst[e];
            float w = rsqrtf((float)max(g_cnt[CNT_PT_SRC + sI], 1)) *
                      rsqrtf((float)max(g_cnt[CNT_PT_DST + dI], 1));
            float4 v = *reinterpret_cast<const float4*>(g_feat_pt + (size_t)sI*D + j*4);
            v.x *= w; v.y *= w; v.z *= w; v.w *= w;
            red_add_v4(out_gcell + (size_t)dI*D + j*4, v);
        }
        return;
    }
    // ---- NNConv scatters (both into cell region) ----
    int t = (b - B_EDGE) * 256 + threadIdx.x;
    int e = t >> 3, j = t & 7;
#pragma unroll
    for (int gph = 0; gph < 2; gph++) {
        const float* ef  = gph == 0 ? pin_feat   : edge_feat;
        const int*   src = gph == 0 ? pinned_src : pf_src;
        const int*   dst = gph == 0 ? pinned_dst : pf_dst;
        const float* M   = gph == 0 ? g_Mnet     : g_Mhan;
        const float* c   = gph == 0 ? g_cnet     : g_chan;
        const int*   cnt = gph == 0 ? g_cnt + CNT_PINNED_DST : g_cnt + CNT_PF_DST;

        int sI = src[e], dI = dst[e];
        float inv = 1.f / (float)max(cnt[dI], 1);

        const float4* efp = reinterpret_cast<const float4*>(ef + (size_t)e * DP);
        float4 e0 = efp[0], e1 = efp[1], e2 = efp[2], e3 = efp[3];
        float efv[DP] = { e0.x, e0.y, e0.z, e0.w, e1.x, e1.y, e1.z, e1.w,
                          e2.x, e2.y, e2.z, e2.w, e3.x, e3.y, e3.z, e3.w };

        const float* Mrow = M + (size_t)sI * (DP*D) + j*4;
        float4 acc = *reinterpret_cast<const float4*>(c + (size_t)sI*D + j*4);
#pragma unroll
        for (int p = 0; p < DP; p++) {
            float4 mv = *reinterpret_cast<const float4*>(Mrow + p*D);
            acc.x += efv[p] * mv.x; acc.y += efv[p] * mv.y;
            acc.z += efv[p] * mv.z; acc.w += efv[p] * mv.w;
        }
        acc.x *= inv; acc.y *= inv; acc.z *= inv; acc.w *= inv;
        red_add_v4(out + (size_t)dI*D + j*4, acc);
    }
}

// =====================================================================
extern "C" void kernel_launch(void* const* d_in, const int* in_sizes, int n_in,
                              void* d_out, int out_size) {
    const float* node_feat  = (const float*)d_in[0];
    const float* net_feat   = (const float*)d_in[1];
    const float* pin_feat   = (const float*)d_in[2];
    const float* hanna_feat = (const float*)d_in[3];
    const float* edge_feat  = (const float*)d_in[4];
    const int* pins_src     = (const int*)d_in[5];
    const int* pins_dst     = (const int*)d_in[6];
    const int* pinned_src   = (const int*)d_in[7];
    const int* pinned_dst   = (const int*)d_in[8];
    const int* connect_src  = (const int*)d_in[9];
    const int* connect_dst  = (const int*)d_in[10];
    const int* pt_src       = (const int*)d_in[11];
    const int* pt_dst       = (const int*)d_in[12];
    const int* pf_src       = (const int*)d_in[13];
    const int* pf_dst       = (const int*)d_in[14];
    const float* W_net      = (const float*)d_in[15];
    const float* b_net      = (const float*)d_in[16];
    const float* W_topo     = (const float*)d_in[17];
    const float* b_topo     = (const float*)d_in[18];
    const float* W_pins     = (const float*)d_in[19];
    const float* b_pins     = (const float*)d_in[20];
    const float* W_connect  = (const float*)d_in[21];
    const float* b_connect  = (const float*)d_in[22];
    const float* W_pt       = (const float*)d_in[23];
    const float* b_pt       = (const float*)d_in[24];
    const float* b_pinned   = (const float*)d_in[25];
    const float* b_pf       = (const float*)d_in[26];
    (void)in_sizes; (void)n_in; (void)out_size;

    float* out = (float*)d_out;

    static bool s_init = false;
    static void* cnt_ptr = nullptr;
    static size_t m_smem = (size_t)(WT_SIZE + D*D + 8*MR*32) * sizeof(float); // 81920
    if (!s_init) {
        cudaGetSymbolAddress(&cnt_ptr, g_cnt);
        cudaFuncSetAttribute(m2_kernel, cudaFuncAttributeMaxDynamicSharedMemorySize, (int)m_smem);
        s_init = true;
    }

    // zero degree counters
    cudaMemsetAsync(cnt_ptr, 0, CNT_TOTAL * sizeof(int));

    // fused phase A: counting + output init + all small GEMMs
    prep_kernel<<<B_PREP, 256>>>(pins_src, pins_dst, pinned_dst,
                                 connect_src, connect_dst, pt_src, pt_dst, pf_dst,
                                 node_feat, net_feat, hanna_feat,
                                 W_net, b_net, W_pins, b_pins, W_connect, b_connect,
                                 W_pt, b_pt, b_pinned, b_pf, out);

    // per-node NNConv matrices
    const int NGROUPS = (N_NET + N_GCELL) / MR;        // 7500
    m2_kernel<<<(NGROUPS + 7)/8, 256, m_smem>>>(net_feat, hanna_feat, W_topo, b_topo);

    // fused edge scatters
    edge_kernel<<<2*B_EDGE, 256>>>(pins_src, pins_dst, connect_src, connect_dst,
                                   pt_src, pt_dst, pin_feat, pinned_src, pinned_dst,
                                   edge_feat, pf_src, pf_dst, out);
}

// round 4
// speedup vs baseline: 1.6948x; 1.4113x over previous
#include <cuda_runtime.h>
#include <cuda_fp16.h>

#define N_CELL 50000
#define N_NET  10000
#define N_GCELL 20000
#define NE 100000
#define D 32
#define DP 16

#define OUT_NET_OFF   (N_CELL*D)            // 1,600,000
#define OUT_GCELL_OFF ((N_CELL+N_NET)*D)    // 1,920,000

// degree counter layout inside g_cnt
#define CNT_PINS_SRC   0         // N_CELL
#define CNT_PINS_DST   50000     // N_NET
#define CNT_PINNED_DST 60000     // N_CELL
#define CNT_CONN_SRC   110000    // N_GCELL
#define CNT_CONN_DST   130000    // N_GCELL
#define CNT_PT_SRC     150000    // N_CELL
#define CNT_PT_DST     200000    // N_GCELL
#define CNT_PF_DST     220000    // N_CELL
#define CNT_TOTAL      270000

#define WT_PAD 18                 // [i][o][p] smem layout, o-stride 18 (16 p + 2 pad)
#define WT_SIZE (D * D * WT_PAD)  // 18432 floats

// ---------------- scratch (device globals; no allocation allowed) ----------
__device__ int   g_cnt[CNT_TOTAL];
__device__ float g_feat_pins[N_CELL*D];   // node @ W_pins (unscaled)
__device__ float g_feat_pt[N_CELL*D];     // node @ W_pt   (unscaled)
__device__ float g_feat_conn[N_GCELL*D];  // hanna @ W_connect (unscaled)
__device__ __align__(16) __half g_Mnet_h[N_NET*DP*D];   // [n][p][o] fp16
__device__ float g_cnet[N_NET*D];
__device__ __align__(16) __half g_Mhan_h[N_GCELL*DP*D]; // [n][p][o] fp16
__device__ float g_chan[N_GCELL*D];

__device__ __forceinline__ void red_add_v4(float* p, float4 v) {
    asm volatile("red.global.add.v4.f32 [%0], {%1,%2,%3,%4};"
                 :: "l"(p), "f"(v.x), "f"(v.y), "f"(v.z), "f"(v.w) : "memory");
}
__device__ __forceinline__ unsigned long long pack2(float x, float y) {
    unsigned long long r;
    asm("mov.b64 %0, {%1,%2};" : "=l"(r) : "f"(x), "f"(y));
    return r;
}
__device__ __forceinline__ void unpack2(unsigned long long v, float& x, float& y) {
    asm("mov.b64 {%0,%1}, %2;" : "=f"(x), "=f"(y) : "l"(v));
}
__device__ __forceinline__ unsigned long long fma2(unsigned long long a,
                                                   unsigned long long b,
                                                   unsigned long long c) {
    unsigned long long d;
    asm("fma.rn.f32x2 %0, %1, %2, %3;" : "=l"(d) : "l"(a), "l"(b), "l"(c));
    return d;
}

// =============== fused prep: count | bias init | net init | node feats | conn feats ========
// GEMM regions: 32 rows per block (8 warps x 4 rows), f32x2 over row pairs, h via LDS broadcast.
#define B_COUNT 391                      // ceil(NE/256)
#define B_BIAS  2188                     // ceil((N_CELL+N_GCELL)*D/4 / 256) float4 writes
#define B_NET   313                      // ceil(N_NET/32)
#define B_NODE  1563                     // ceil(N_CELL/32)
#define B_CONN  625                      // N_GCELL/32
#define B_PREP  (B_COUNT + B_BIAS + B_NET + B_NODE + B_CONN)   // 5080

__global__ void prep_kernel(const int* __restrict__ pins_src, const int* __restrict__ pins_dst,
                            const int* __restrict__ pinned_dst,
                            const int* __restrict__ conn_src, const int* __restrict__ conn_dst,
                            const int* __restrict__ pt_src, const int* __restrict__ pt_dst,
                            const int* __restrict__ pf_dst,
                            const float* __restrict__ node_feat, const float* __restrict__ net_feat,
                            const float* __restrict__ hanna_feat,
                            const float* __restrict__ W_net, const float* __restrict__ b_net,
                            const float* __restrict__ W_pins, const float* __restrict__ b_pins,
                            const float* __restrict__ W_connect, const float* __restrict__ b_connect,
                            const float* __restrict__ W_pt, const float* __restrict__ b_pt,
                            const float* __restrict__ b_pinned, const float* __restrict__ b_pf,
                            float* __restrict__ out) {
    __shared__ float sA[D*D], sB[D*D];
    __shared__ float sH[8*4*32];          // 8 warps * 4 rows * 32
    int b = blockIdx.x;

    if (b < B_COUNT) {
        // ---- degree counting ----
        int e = b * 256 + threadIdx.x;
        if (e >= NE) return;
        atomicAdd(&g_cnt[CNT_PINS_SRC   + pins_src[e]],   1);
        atomicAdd(&g_cnt[CNT_PINS_DST   + pins_dst[e]],   1);
        atomicAdd(&g_cnt[CNT_PINNED_DST + pinned_dst[e]], 1);
        atomicAdd(&g_cnt[CNT_CONN_SRC   + conn_src[e]],   1);
        atomicAdd(&g_cnt[CNT_CONN_DST   + conn_dst[e]],   1);
        atomicAdd(&g_cnt[CNT_PT_SRC     + pt_src[e]],     1);
        atomicAdd(&g_cnt[CNT_PT_DST     + pt_dst[e]],     1);
        atomicAdd(&g_cnt[CNT_PF_DST     + pf_dst[e]],     1);
        return;
    }
    b -= B_COUNT;

    if (b < B_BIAS) {
        // ---- bias init of cell + gcell output regions (float4) ----
        int i = b * 256 + threadIdx.x;                    // float4 index
        const int n_cell_v4 = N_CELL * D / 4;             // 400000
        const int n_gcell_v4 = N_GCELL * D / 4;           // 160000
        if (i < n_cell_v4) {
            int o = (i*4) & (D-1);
            float4 v = make_float4(b_pinned[o] + b_pf[o],   b_pinned[o+1] + b_pf[o+1],
                                   b_pinned[o+2] + b_pf[o+2], b_pinned[o+3] + b_pf[o+3]);
            reinterpret_cast<float4*>(out)[i] = v;
        } else if (i < n_cell_v4 + n_gcell_v4) {
            int k = i - n_cell_v4;
            int o = (k*4) & (D-1);
            float4 v = make_float4(b_connect[o] + b_pt[o],   b_connect[o+1] + b_pt[o+1],
                                   b_connect[o+2] + b_pt[o+2], b_connect[o+3] + b_pt[o+3]);
            reinterpret_cast<float4*>(out + OUT_GCELL_OFF)[k] = v;
        }
        return;
    }
    b -= B_BIAS;

    int wid = threadIdx.x >> 5, lane = threadIdx.x & 31;
    int hbase = wid * 128;

    if (b < B_NET) {
        // ---- out_net = net_feat @ W_net + b_net + b_pins ----
        for (int i = threadIdx.x; i < D*D; i += 256) sA[i] = W_net[i];
        __syncthreads();
        int r0 = b * 32 + wid * 4;
#pragma unroll
        for (int r = 0; r < 4; r++) {
            int row = r0 + r;
            sH[hbase + r*32 + lane] = (row < N_NET) ? net_feat[row*D + lane] : 0.f;
        }
        __syncwarp();
        float bv = b_net[lane] + b_pins[lane];
        unsigned long long a01 = pack2(bv, bv), a23 = pack2(bv, bv);
#pragma unroll
        for (int i = 0; i < D; i++) {
            float w = sA[i*D + lane];
            unsigned long long wp = pack2(w, w);
            a01 = fma2(pack2(sH[hbase + i], sH[hbase + 32 + i]), wp, a01);
            a23 = fma2(pack2(sH[hbase + 64 + i], sH[hbase + 96 + i]), wp, a23);
        }
        float x0, x1, x2, x3;
        unpack2(a01, x0, x1); unpack2(a23, x2, x3);
        if (r0 + 0 < N_NET) out[OUT_NET_OFF + (r0+0)*D + lane] = x0;
        if (r0 + 1 < N_NET) out[OUT_NET_OFF + (r0+1)*D + lane] = x1;
        if (r0 + 2 < N_NET) out[OUT_NET_OFF + (r0+2)*D + lane] = x2;
        if (r0 + 3 < N_NET) out[OUT_NET_OFF + (r0+3)*D + lane] = x3;
        return;
    }
    b -= B_NET;

    if (b < B_NODE) {
        // ---- node feats: g_feat_pins = node@W_pins, g_feat_pt = node@W_pt ----
        for (int i = threadIdx.x; i < D*D; i += 256) { sA[i] = W_pins[i]; sB[i] = W_pt[i]; }
        __syncthreads();
        int r0 = b * 32 + wid * 4;
#pragma unroll
        for (int r = 0; r < 4; r++) {
            int row = r0 + r;
            sH[hbase + r*32 + lane] = (row < N_CELL) ? node_feat[row*D + lane] : 0.f;
        }
        __syncwarp();
        unsigned long long p01 = 0ull, p23 = 0ull, q01 = 0ull, q23 = 0ull;
#pragma unroll
        for (int i = 0; i < D; i++) {
            unsigned long long h01 = pack2(sH[hbase + i], sH[hbase + 32 + i]);
            unsigned long long h23 = pack2(sH[hbase + 64 + i], sH[hbase + 96 + i]);
            float wa = sA[i*D + lane];
            unsigned long long wap = pack2(wa, wa);
            float wb = sB[i*D + lane];
            unsigned long long wbp = pack2(wb, wb);
            p01 = fma2(h01, wap, p01); p23 = fma2(h23, wap, p23);
            q01 = fma2(h01, wbp, q01); q23 = fma2(h23, wbp, q23);
        }
        float x0, x1, x2, x3, y0, y1, y2, y3;
        unpack2(p01, x0, x1); unpack2(p23, x2, x3);
        unpack2(q01, y0, y1); unpack2(q23, y2, y3);
        if (r0 + 0 < N_CELL) { g_feat_pins[(r0+0)*D + lane] = x0; g_feat_pt[(r0+0)*D + lane] = y0; }
        if (r0 + 1 < N_CELL) { g_feat_pins[(r0+1)*D + lane] = x1; g_feat_pt[(r0+1)*D + lane] = y1; }
        if (r0 + 2 < N_CELL) { g_feat_pins[(r0+2)*D + lane] = x2; g_feat_pt[(r0+2)*D + lane] = y2; }
        if (r0 + 3 < N_CELL) { g_feat_pins[(r0+3)*D + lane] = x3; g_feat_pt[(r0+3)*D + lane] = y3; }
        return;
    }
    b -= B_NET - B_NET;   // no-op for clarity
    b -= B_NODE;

    // ---- gcell feats: g_feat_conn = hanna@W_connect ----
    for (int i = threadIdx.x; i < D*D; i += 256) sA[i] = W_connect[i];
    __syncthreads();
    int r0 = b * 32 + wid * 4;
#pragma unroll
    for (int r = 0; r < 4; r++) {
        int row = r0 + r;
        sH[hbase + r*32 + lane] = (row < N_GCELL) ? hanna_feat[row*D + lane] : 0.f;
    }
    __syncwarp();
    unsigned long long a01 = 0ull, a23 = 0ull;
#pragma unroll
    for (int i = 0; i < D; i++) {
        float w = sA[i*D + lane];
        unsigned long long wp = pack2(w, w);
        a01 = fma2(pack2(sH[hbase + i], sH[hbase + 32 + i]), wp, a01);
        a23 = fma2(pack2(sH[hbase + 64 + i], sH[hbase + 96 + i]), wp, a23);
    }
    float x0, x1, x2, x3;
    unpack2(a01, x0, x1); unpack2(a23, x2, x3);
    g_feat_conn[(r0+0)*D + lane] = x0;
    g_feat_conn[(r0+1)*D + lane] = x1;
    g_feat_conn[(r0+2)*D + lane] = x2;
    g_feat_conn[(r0+3)*D + lane] = x3;
}

// ------------- per-node NNConv matrices via packed f32x2, stored fp16 -----------
// M_n[p,o] = sum_i h_n[i]*W_topo[p, i*D+o];   c_n[o] = sum_i h_n[i]*b_topo[i*D+o]
#define MR 4
__global__ void m2_kernel(const float* __restrict__ net_feat, const float* __restrict__ hanna_feat,
                          const float* __restrict__ W_topo, const float* __restrict__ b_topo) {
    extern __shared__ float s[];
    float* sW2 = s;                 // WT_SIZE = 18432 floats
    float* sb  = s + WT_SIZE;       // 1024
    float* sH  = s + WT_SIZE + D*D; // 8 warps * MR * 32 = 1024
    for (int t = threadIdx.x; t < DP*D*D; t += blockDim.x) {
        int p = t >> 10;          // t / (D*D)
        int rem = t & 1023;
        int i = rem >> 5;
        int o = rem & 31;
        sW2[i*(D*WT_PAD) + o*WT_PAD + p] = W_topo[t];
    }
    for (int i = threadIdx.x; i < D*D; i += blockDim.x) sb[i] = b_topo[i];
    __syncthreads();

    int wid = threadIdx.x >> 5, lane = threadIdx.x & 31;
    int g = blockIdx.x * 8 + wid;            // group of MR rows
    const int NGROUPS = (N_NET + N_GCELL) / MR;  // 7500
    if (g >= NGROUPS) return;
    int r0 = g * MR;
    int hbase = wid * (MR*32);

    __half* Mout[MR];
    float* cout[MR];
#pragma unroll
    for (int r = 0; r < MR; r++) {
        int row = r0 + r;
        float hv;
        if (row < N_NET) {
            hv = net_feat[row*D + lane];
            Mout[r] = g_Mnet_h + (size_t)row * (DP*D);
            cout[r] = g_cnet + (size_t)row * D;
        } else {
            int rr = row - N_NET;
            hv = hanna_feat[rr*D + lane];
            Mout[r] = g_Mhan_h + (size_t)rr * (DP*D);
            cout[r] = g_chan + (size_t)rr * D;
        }
        sH[hbase + r*32 + lane] = hv;
    }
    __syncwarp();

    unsigned long long acc[MR][DP/2];
    float cacc[MR];
#pragma unroll
    for (int r = 0; r < MR; r++) {
        cacc[r] = 0.f;
#pragma unroll
        for (int pp = 0; pp < DP/2; pp++) acc[r][pp] = 0ull;
    }

#pragma unroll
    for (int i = 0; i < D; i++) {
        unsigned long long hp[MR];
        float bv = sb[i*D + lane];
#pragma unroll
        for (int r = 0; r < MR; r++) {
            float hv = sH[hbase + r*32 + i];
            hp[r] = pack2(hv, hv);
            cacc[r] += hv * bv;
        }
        const unsigned long long* wrow =
            reinterpret_cast<const unsigned long long*>(sW2 + i*(D*WT_PAD) + lane*WT_PAD);
#pragma unroll
        for (int pp = 0; pp < DP/2; pp++) {
            unsigned long long wv = wrow[pp];
#pragma unroll
            for (int r = 0; r < MR; r++) acc[r][pp] = fma2(hp[r], wv, acc[r][pp]);
        }
    }

#pragma unroll
    for (int r = 0; r < MR; r++) {
#pragma unroll
        for (int pp = 0; pp < DP/2; pp++) {
            float x, y;
            unpack2(acc[r][pp], x, y);
            Mout[r][(2*pp)*D + lane]   = __float2half_rn(x);
            Mout[r][(2*pp+1)*D + lane] = __float2half_rn(y);
        }
        cout[r][lane] = cacc[r];
    }
}

// ------------- fused edge scatter: blocks [0,B_EDGE) = GraphConvs, rest = NNConvs ----
#define B_EDGE 3125                                     // NE*8/256

__global__ void edge_kernel(const int* __restrict__ pins_src, const int* __restrict__ pins_dst,
                            const int* __restrict__ conn_src, const int* __restrict__ conn_dst,
                            const int* __restrict__ pt_src, const int* __restrict__ pt_dst,
                            const float* __restrict__ pin_feat,
                            const int* __restrict__ pinned_src, const int* __restrict__ pinned_dst,
                            const float* __restrict__ edge_feat,
                            const int* __restrict__ pf_src, const int* __restrict__ pf_dst,
                            float* __restrict__ out) {
    int b = blockIdx.x;
    if (b < B_EDGE) {
        // ---- GraphConv scatters ----
        int t = b * 256 + threadIdx.x;
        int e = t >> 3, j = t & 7;
        float* out_net   = out + OUT_NET_OFF;
        float* out_gcell = out + OUT_GCELL_OFF;
        // pins: cell -> net
        {
            int sI = pins_src[e], dI = pins_dst[e];
            float w = rsqrtf((float)max(g_cnt[CNT_PINS_SRC + sI], 1)) *
                      rsqrtf((float)max(g_cnt[CNT_PINS_DST + dI], 1));
            float4 v = *reinterpret_cast<const float4*>(g_feat_pins + (size_t)sI*D + j*4);
            v.x *= w; v.y *= w; v.z *= w; v.w *= w;
            red_add_v4(out_net + (size_t)dI*D + j*4, v);
        }
        // connect: gcell -> gcell
        {
            int sI = conn_src[e], dI = conn_dst[e];
            float w = rsqrtf((float)max(g_cnt[CNT_CONN_SRC + sI], 1)) *
                      rsqrtf((float)max(g_cnt[CNT_CONN_DST + dI], 1));
            float4 v = *reinterpret_cast<const float4*>(g_feat_conn + (size_t)sI*D + j*4);
            v.x *= w; v.y *= w; v.z *= w; v.w *= w;
            red_add_v4(out_gcell + (size_t)dI*D + j*4, v);
        }
        // pt: cell -> gcell
        {
            int sI = pt_src[e], dI = pt_dst[e];
            float w = rsqrtf((float)max(g_cnt[CNT_PT_SRC + sI], 1)) *
                      rsqrtf((float)max(g_cnt[CNT_PT_DST + dI], 1));
            float4 v = *reinterpret_cast<const float4*>(g_feat_pt + (size_t)sI*D + j*4);
            v.x *= w; v.y *= w; v.z *= w; v.w *= w;
            red_add_v4(out_gcell + (size_t)dI*D + j*4, v);
        }
        return;
    }
    // ---- NNConv scatters (both into cell region), M in fp16 ----
    int t = (b - B_EDGE) * 256 + threadIdx.x;
    int e = t >> 3, j = t & 7;
#pragma unroll
    for (int gph = 0; gph < 2; gph++) {
        const float* ef   = gph == 0 ? pin_feat   : edge_feat;
        const int*   src  = gph == 0 ? pinned_src : pf_src;
        const int*   dst  = gph == 0 ? pinned_dst : pf_dst;
        const __half* M   = gph == 0 ? g_Mnet_h   : g_Mhan_h;
        const float* c    = gph == 0 ? g_cnet     : g_chan;
        const int*   cnt  = gph == 0 ? g_cnt + CNT_PINNED_DST : g_cnt + CNT_PF_DST;

        int sI = src[e], dI = dst[e];
        float inv = 1.f / (float)max(cnt[dI], 1);

        const float4* efp = reinterpret_cast<const float4*>(ef + (size_t)e * DP);
        float4 e0 = efp[0], e1 = efp[1], e2 = efp[2], e3 = efp[3];
        float efv[DP] = { e0.x, e0.y, e0.z, e0.w, e1.x, e1.y, e1.z, e1.w,
                          e2.x, e2.y, e2.z, e2.w, e3.x, e3.y, e3.z, e3.w };

        const __half* Mrow = M + (size_t)sI * (DP*D) + j*4;
        float4 acc = *reinterpret_cast<const float4*>(c + (size_t)sI*D + j*4);
#pragma unroll
        for (int p = 0; p < DP; p++) {
            float2 raw = *reinterpret_cast<const float2*>(Mrow + p*D);  // 4 halves
            __half2 h01 = *reinterpret_cast<__half2*>(&raw.x);
            __half2 h23 = *reinterpret_cast<__half2*>(&raw.y);
            float2 m01 = __half22float2(h01);
            float2 m23 = __half22float2(h23);
            acc.x += efv[p] * m01.x; acc.y += efv[p] * m01.y;
            acc.z += efv[p] * m23.x; acc.w += efv[p] * m23.y;
        }
        acc.x *= inv; acc.y *= inv; acc.z *= inv; acc.w *= inv;
        red_add_v4(out + (size_t)dI*D + j*4, acc);
    }
}

// =====================================================================
extern "C" void kernel_launch(void* const* d_in, const int* in_sizes, int n_in,
                              void* d_out, int out_size) {
    const float* node_feat  = (const float*)d_in[0];
    const float* net_feat   = (const float*)d_in[1];
    const float* pin_feat   = (const float*)d_in[2];
    const float* hanna_feat = (const float*)d_in[3];
    const float* edge_feat  = (const float*)d_in[4];
    const int* pins_src     = (const int*)d_in[5];
    const int* pins_dst     = (const int*)d_in[6];
    const int* pinned_src   = (const int*)d_in[7];
    const int* pinned_dst   = (const int*)d_in[8];
    const int* connect_src  = (const int*)d_in[9];
    const int* connect_dst  = (const int*)d_in[10];
    const int* pt_src       = (const int*)d_in[11];
    const int* pt_dst       = (const int*)d_in[12];
    const int* pf_src       = (const int*)d_in[13];
    const int* pf_dst       = (const int*)d_in[14];
    const float* W_net      = (const float*)d_in[15];
    const float* b_net      = (const float*)d_in[16];
    const float* W_topo     = (const float*)d_in[17];
    const float* b_topo     = (const float*)d_in[18];
    const float* W_pins     = (const float*)d_in[19];
    const float* b_pins     = (const float*)d_in[20];
    const float* W_connect  = (const float*)d_in[21];
    const float* b_connect  = (const float*)d_in[22];
    const float* W_pt       = (const float*)d_in[23];
    const float* b_pt       = (const float*)d_in[24];
    const float* b_pinned   = (const float*)d_in[25];
    const float* b_pf       = (const float*)d_in[26];
    (void)in_sizes; (void)n_in; (void)out_size;

    float* out = (float*)d_out;

    static bool s_init = false;
    static void* cnt_ptr = nullptr;
    static size_t m_smem = (size_t)(WT_SIZE + D*D + 8*MR*32) * sizeof(float); // 81920
    if (!s_init) {
        cudaGetSymbolAddress(&cnt_ptr, g_cnt);
        cudaFuncSetAttribute(m2_kernel, cudaFuncAttributeMaxDynamicSharedMemorySize, (int)m_smem);
        s_init = true;
    }

    // zero degree counters
    cudaMemsetAsync(cnt_ptr, 0, CNT_TOTAL * sizeof(int));

    // fused phase A: counting + output init + all small GEMMs
    prep_kernel<<<B_PREP, 256>>>(pins_src, pins_dst, pinned_dst,
                                 connect_src, connect_dst, pt_src, pt_dst, pf_dst,
                                 node_feat, net_feat, hanna_feat,
                                 W_net, b_net, W_pins, b_pins, W_connect, b_connect,
                                 W_pt, b_pt, b_pinned, b_pf, out);

    // per-node NNConv matrices (fp16 output)
    const int NGROUPS = (N_NET + N_GCELL) / MR;        // 7500
    m2_kernel<<<(NGROUPS + 7)/8, 256, m_smem>>>(net_feat, hanna_feat, W_topo, b_topo);

    // fused edge scatters
    edge_kernel<<<2*B_EDGE, 256>>>(pins_src, pins_dst, connect_src, connect_dst,
                                   pt_src, pt_dst, pin_feat, pinned_src, pinned_dst,
                                   edge_feat, pf_src, pf_dst, out);
}